// round 16
// baseline (speedup 1.0000x reference)
#include <cuda_runtime.h>
#include <cuda_fp16.h>
#include <math.h>

#define NN 50000
#define NNP 50176
#define EE 1600000
#define RR 8
#define HIDC 64
#define OUTC 40

// pi layout: stored half position p -> true column
// p = nh*32 + tq*8 + nt*2 + e  ->  col = (nh*4+nt)*8 + tq*2 + e
#define PIDX(p) ((((((p) >> 5) & 1) << 2) + (((p) >> 1) & 3)) * 8 + \
                 ((((p) >> 3) & 3) << 1) + ((p) & 1))
#define SWZ(boff) ((boff) ^ (((boff) >> 3) & 0x70))

// ---------------- scratch (vector-accessed arrays force-aligned) ---------------
__device__ __align__(16) __half g_h[(size_t)RR * NN * HIDC];  // h (fp16, pi-order cols)
__device__ __align__(16) __half g_xh[(size_t)NNP * HIDC];     // layer-2 input (fp16, pi)
__device__ __align__(16) __half g_y2h[(size_t)NN * HIDC];     // layer-2 output (fp16, pi)
__device__ __align__(16) float g_qk[(size_t)NN * 16];         // qn (0..7), kn (8..15)
__device__ __align__(16) __half g_whA[RR * HIDC * HIDC];      // W1 fp16
__device__ __align__(16) __half g_whB[RR * HIDC * HIDC];      // W2 fp16 (rows pi-permuted)
__device__ __align__(16) __half g_wqkhA[64 * 16];             // layer-1 wqk matrix
__device__ __align__(16) __half g_wqkhB[64 * 16];             // layer-2 wqk matrix

// CSR-by-dst (g_csr padded by 32 zero entries for branch-free tails)
__device__ int g_deg[NN];
__device__ int g_rowptr[NN + 1];
__device__ int g_cursor[NN];
__device__ int g_csr[EE + 32];                   // src | (rel << 16); pad stays 0

// decoupled-lookback scan state (g_bflag memset to 0 each launch)
__device__ int g_bflag[128];                      // 0=none, 1=agg ready, 2=incl ready
__device__ int g_agg[128];
__device__ int g_incp[128];

// ---------------- k_pre: degree histogram + W1/W2 fp16 conversion + wqk --------
__global__ void k_pre(const int* __restrict__ ei,
                      const float* __restrict__ W1, const float* __restrict__ q1,
                      const float* __restrict__ k1,
                      const float* __restrict__ W2, const float* __restrict__ q2,
                      const float* __restrict__ k2) {
    int b = blockIdx.x, t = threadIdx.x;
    if (b < EE / 256) {                    // 6250 blocks: degree histogram
        int e = b * 256 + t;
        atomicAdd(&g_deg[ei[EE + e]], 1);
        return;
    }
    int rb = b - EE / 256;                 // 0..15
    int r = rb & 7, layer = rb >> 3;
    const float* W = layer ? W2 : W1;
    const float* q = layer ? q2 : q1;
    const float* kk = layer ? k2 : k1;
    __half* wh = layer ? g_whB : g_whA;
    __half* wqk = layer ? g_wqkhB : g_wqkhA;
    int perm = layer;                      // layer-2 input is pi-permuted
    for (int i = t; i < 4096; i += 256) {
        int p = i >> 6, c = i & 63;
        int s = perm ? PIDX(p) : p;
        wh[r * 4096 + p * 64 + c] = __float2half_rn(W[(size_t)r * 4096 + s * 64 + c]);
    }
    if (t < 64) {
        int s = perm ? PIDX(t) : t;
        const float* Wr = W + ((size_t)r * 64 + s) * 64;
        float aq = 0.f, ak = 0.f;
        #pragma unroll
        for (int c = 0; c < 64; c++) {
            float w = Wr[c];
            aq += w * q[r * 64 + c];
            ak += w * kk[r * 64 + c];
        }
        wqk[t * 16 + r]     = __float2half_rn(aq);
        wqk[t * 16 + 8 + r] = __float2half_rn(ak);
    }
}

// ---------------- single-pass scan over g_deg (98 blocks, all resident) --------
__global__ void __launch_bounds__(512) k_scan() {
    __shared__ int s[512];
    __shared__ int s_prefix;
    volatile int* vflag = g_bflag;
    volatile int* vagg  = g_agg;
    volatile int* vincp = g_incp;
    int t = threadIdx.x, b = blockIdx.x;
    int idx = b * 512 + t;
    int dv = (idx < NN) ? g_deg[idx] : 0;
    s[t] = dv;
    __syncthreads();
    #pragma unroll
    for (int off = 1; off < 512; off <<= 1) {
        int v = (t >= off) ? s[t - off] : 0;
        __syncthreads();
        s[t] += v;
        __syncthreads();
    }
    if (t == 511) {
        int total = s[511];
        if (b == 0) {
            vincp[0] = total;
            __threadfence();
            vflag[0] = 2;
            s_prefix = 0;
        } else {
            vagg[b] = total;
            __threadfence();
            vflag[b] = 1;
            int run = 0;
            for (int p = b - 1; p >= 0;) {
                int f;
                do { f = vflag[p]; } while (f == 0);
                __threadfence();
                if (f == 2) { run += vincp[p]; break; }
                run += vagg[p];
                p--;
            }
            s_prefix = run;
            vincp[b] = run + total;
            __threadfence();
            vflag[b] = 2;
        }
    }
    __syncthreads();
    int off = s_prefix;
    if (idx < NN) {
        int rp = s[t] - dv + off;
        g_rowptr[idx] = rp;
        g_cursor[idx] = rp;
    }
    if (idx == 0) g_rowptr[NN] = EE;
}

__global__ void k_scatter(const int* __restrict__ ei, const int* __restrict__ et) {
    int e = blockIdx.x * blockDim.x + threadIdx.x;
    if (e >= EE) return;
    int d = ei[EE + e];
    int pos = atomicAdd(&g_cursor[d], 1);
    g_csr[pos] = ei[e] | (et[e] << 16);
}

// ---------------- relation-per-warp HMMA GEMM + MMA-computed qn/kn -------------
__device__ __forceinline__ void ldsm4(unsigned addr, unsigned& r0, unsigned& r1,
                                      unsigned& r2, unsigned& r3) {
    asm volatile("ldmatrix.sync.aligned.m8n8.x4.shared.b16 {%0,%1,%2,%3}, [%4];"
                 : "=r"(r0), "=r"(r1), "=r"(r2), "=r"(r3) : "r"(addr));
}
__device__ __forceinline__ void ldsm4t(unsigned addr, unsigned& r0, unsigned& r1,
                                       unsigned& r2, unsigned& r3) {
    asm volatile("ldmatrix.sync.aligned.m8n8.x4.trans.shared.b16 {%0,%1,%2,%3}, [%4];"
                 : "=r"(r0), "=r"(r1), "=r"(r2), "=r"(r3) : "r"(addr));
}
__device__ __forceinline__ void mma_f16(float* c, unsigned a0, unsigned a1,
                                        unsigned a2, unsigned a3,
                                        unsigned b0, unsigned b1) {
    asm volatile(
        "mma.sync.aligned.m16n8k16.row.col.f32.f16.f16.f32 "
        "{%0,%1,%2,%3}, {%4,%5,%6,%7}, {%8,%9}, {%0,%1,%2,%3};"
        : "+f"(c[0]), "+f"(c[1]), "+f"(c[2]), "+f"(c[3])
        : "r"(a0), "r"(a1), "r"(a2), "r"(a3), "r"(b0), "r"(b1));
}

extern __shared__ char s_dyn[];
#define KH_SMEM (16384 + 65536 + 8192)

// Warp w owns relation w; B-fragments loaded once per n-half, reused over 8 m-tiles.
// layer 0: stage X from fp32 x (convert inline); layer 1: stage from g_xh.
__global__ void __launch_bounds__(256) k_h2(const float* __restrict__ x32, int layer) {
    char* Xs  = s_dyn;                  // 128 x 64 half, swizzled (16 KB)
    char* Ws  = s_dyn + 16384;          // 8 x (64 x 64 half), swizzled (64 KB)
    char* QKs = s_dyn + 16384 + 65536;  // 64 x 16 half, 128B swizzled rows (8 KB)
    const __half* wh = layer ? g_whB : g_whA;
    const __half* wqk = layer ? g_wqkhB : g_wqkhA;
    int n0 = blockIdx.x * 128;
    int tid = threadIdx.x;
    int w = tid >> 5, lane = tid & 31;

    // ---- stage X tile ----
    if (layer) {                        // fp16 padded g_xh: always in-bounds
        const uint4* Xg = (const uint4*)g_xh;
        #pragma unroll
        for (int i = tid; i < 1024; i += 256) {
            int row = i >> 3, c = i & 7;
            *(uint4*)(Xs + SWZ(row * 128 + c * 16)) = Xg[(size_t)(n0 + row) * 8 + c];
        }
    } else {                            // fp32 x -> fp16, bounds-checked
        #pragma unroll
        for (int i = tid; i < 1024; i += 256) {
            int row = i >> 3, c = i & 7;
            int n = n0 + row;
            uint4 u = make_uint4(0, 0, 0, 0);
            if (n < NN) {
                const float4* src = (const float4*)(x32 + (size_t)n * HIDC + c * 8);
                float4 va = src[0], vb = src[1];
                ((__half2*)&u)[0] = __floats2half2_rn(va.x, va.y);
                ((__half2*)&u)[1] = __floats2half2_rn(va.z, va.w);
                ((__half2*)&u)[2] = __floats2half2_rn(vb.x, vb.y);
                ((__half2*)&u)[3] = __floats2half2_rn(vb.z, vb.w);
            }
            *(uint4*)(Xs + SWZ(row * 128 + c * 16)) = u;
        }
    }
    // ---- stage all 8 W (fp16 global, L2 resident) ----
    const uint4* Wg = (const uint4*)wh;
    #pragma unroll
    for (int i = tid; i < 4096; i += 256) {
        int r = i >> 9, row = (i >> 3) & 63, c = i & 7;
        *(uint4*)(Ws + r * 8192 + SWZ(row * 128 + c * 16)) = Wg[i];
    }
    // ---- stage wqk tile ----
    if (tid < 128) {
        int row = tid >> 1, c = tid & 1;
        *(uint4*)(QKs + SWZ(row * 128 + c * 16)) = ((const uint4*)wqk)[tid];
    }
    __syncthreads();

    int j = lane & 7, mat = lane >> 3;
    int mrow = ((mat & 1) << 3) + j;
    int kcol = (mat & 2) << 2;

    unsigned xb  = (unsigned)__cvta_generic_to_shared(Xs);
    unsigned wb  = (unsigned)__cvta_generic_to_shared(Ws);
    unsigned qkb = (unsigned)__cvta_generic_to_shared(QKs);

    int g4 = lane >> 2, tq = lane & 3;
    unsigned wrb = wb + w * 8192;       // this warp's relation
    __half* hb = g_h + (size_t)w * NN * HIDC;

    #pragma unroll
    for (int nh = 0; nh < 2; nh++) {
        // B-fragments for this relation's n-half: kept in registers
        unsigned bf[4][4][2];
        #pragma unroll
        for (int kk = 0; kk < 4; kk++) {
            #pragma unroll
            for (int nbl = 0; nbl < 2; nbl++) {
                int nb = nh * 2 + nbl;
                ldsm4t(wrb + SWZ((kk * 16 + mrow) * 128 + (nb * 16 + kcol) * 2),
                       bf[kk][2 * nbl][0], bf[kk][2 * nbl][1],
                       bf[kk][2 * nbl + 1][0], bf[kk][2 * nbl + 1][1]);
            }
        }

        #pragma unroll
        for (int mt = 0; mt < 8; mt++) {
            unsigned a[4][4];
            #pragma unroll
            for (int kk = 0; kk < 4; kk++)
                ldsm4(xb + SWZ((mt * 16 + mrow) * 128 + (kk * 16 + kcol) * 2),
                      a[kk][0], a[kk][1], a[kk][2], a[kk][3]);

            float cc[4][4];
            #pragma unroll
            for (int nt = 0; nt < 4; nt++)
                #pragma unroll
                for (int z = 0; z < 4; z++) cc[nt][z] = 0.f;
            #pragma unroll
            for (int kk = 0; kk < 4; kk++)
                #pragma unroll
                for (int nt = 0; nt < 4; nt++)
                    mma_f16(cc[nt], a[kk][0], a[kk][1], a[kk][2], a[kk][3],
                            bf[kk][nt][0], bf[kk][nt][1]);

            int nA = n0 + mt * 16 + g4, nB = nA + 8;

            // qn/kn tile: warp w handles m-tile w (first n-half pass only)
            if (nh == 0 && mt == w) {
                float cq[2][4];
                #pragma unroll
                for (int z = 0; z < 4; z++) { cq[0][z] = 0.f; cq[1][z] = 0.f; }
                #pragma unroll
                for (int kk = 0; kk < 4; kk++) {
                    unsigned q0, q1, q2, q3;
                    ldsm4t(qkb + SWZ((kk * 16 + mrow) * 128 + kcol * 2), q0, q1, q2, q3);
                    mma_f16(cq[0], a[kk][0], a[kk][1], a[kk][2], a[kk][3], q0, q1);
                    mma_f16(cq[1], a[kk][0], a[kk][1], a[kk][2], a[kk][3], q2, q3);
                }
                if (nA < NN) {
                    *(float2*)&g_qk[nA * 16 + tq * 2]     = make_float2(cq[0][0], cq[0][1]);
                    *(float2*)&g_qk[nA * 16 + 8 + tq * 2] = make_float2(cq[1][0], cq[1][1]);
                }
                if (nB < NN) {
                    *(float2*)&g_qk[nB * 16 + tq * 2]     = make_float2(cq[0][2], cq[0][3]);
                    *(float2*)&g_qk[nB * 16 + 8 + tq * 2] = make_float2(cq[1][2], cq[1][3]);
                }
            }

            // epilogue: pi-order store, granule = nh*4 + tq (64B-sector aligned)
            uint4 uA, uB;
            ((__half2*)&uA)[0] = __floats2half2_rn(cc[0][0], cc[0][1]);
            ((__half2*)&uA)[1] = __floats2half2_rn(cc[1][0], cc[1][1]);
            ((__half2*)&uA)[2] = __floats2half2_rn(cc[2][0], cc[2][1]);
            ((__half2*)&uA)[3] = __floats2half2_rn(cc[3][0], cc[3][1]);
            ((__half2*)&uB)[0] = __floats2half2_rn(cc[0][2], cc[0][3]);
            ((__half2*)&uB)[1] = __floats2half2_rn(cc[1][2], cc[1][3]);
            ((__half2*)&uB)[2] = __floats2half2_rn(cc[2][2], cc[2][3]);
            ((__half2*)&uB)[3] = __floats2half2_rn(cc[3][2], cc[3][3]);
            if (nA < NN) ((uint4*)(hb + (size_t)nA * HIDC))[nh * 4 + tq] = uA;
            if (nB < NN) ((uint4*)(hb + (size_t)nB * HIDC))[nh * 4 + tq] = uB;
        }
    }
}

// ---------------- fused softmax + aggregation (one warp per dst) ----------------
__global__ void __launch_bounds__(256, 6) k_gat(const float* __restrict__ b, int dst2) {
    int warp = blockIdx.x * 8 + (threadIdx.x >> 5);
    int lane = threadIdx.x & 31;
    if (warp >= NN) return;
    int g = lane >> 3;
    int l8 = lane & 7;

    int beg = g_rowptr[warp];
    int end = g_rowptr[warp + 1];

    float acc[8];
    #pragma unroll
    for (int c = 0; c < 8; c++) acc[c] = 0.f;
    float dsum = 0.f;
    const uint4* h4 = (const uint4*)g_h;

    for (int base = beg; base < end; base += 32) {
        int i = base + lane;
        int pk = g_csr[i];                     // padded: always valid
        int s = pk & 0xFFFF, r = pk >> 16;
        float a = g_qk[warp * 16 + r] + g_qk[s * 16 + 8 + r];
        a = a > 0.f ? a : 0.2f * a;
        float ex = (i < end) ? __expf(a) : 0.f;
        dsum += ex;

        int cnt = end - base;
        if (cnt >= 32) {
            #pragma unroll
            for (int jj = 0; jj < 32; jj += 4) {
                int idx = jj + g;
                float exj = __shfl_sync(0xffffffffu, ex, idx);
                int pkj = __shfl_sync(0xffffffffu, pk, idx);
                int sj = pkj & 0xFFFF, rj = pkj >> 16;
                uint4 v = h4[((size_t)rj * NN + sj) * 8 + l8];
                float2 f0 = __half22float2(*(__half2*)&v.x);
                float2 f1 = __half22float2(*(__half2*)&v.y);
                float2 f2 = __half22float2(*(__half2*)&v.z);
                float2 f3 = __half22float2(*(__half2*)&v.w);
                acc[0] += exj * f0.x; acc[1] += exj * f0.y;
                acc[2] += exj * f1.x; acc[3] += exj * f1.y;
                acc[4] += exj * f2.x; acc[5] += exj * f2.y;
                acc[6] += exj * f3.x; acc[7] += exj * f3.y;
            }
        } else {
            int ng = (cnt + 3) & ~3;
            for (int jj = 0; jj < ng; jj += 4) {
                int idx = jj + g;
                float exj = __shfl_sync(0xffffffffu, ex, idx);   // 0 for idx >= cnt
                int pkj = __shfl_sync(0xffffffffu, pk, idx);
                int sj = pkj & 0xFFFF, rj = pkj >> 16;
                uint4 v = h4[((size_t)rj * NN + sj) * 8 + l8];
                float2 f0 = __half22float2(*(__half2*)&v.x);
                float2 f1 = __half22float2(*(__half2*)&v.y);
                float2 f2 = __half22float2(*(__half2*)&v.z);
                float2 f3 = __half22float2(*(__half2*)&v.w);
                acc[0] += exj * f0.x; acc[1] += exj * f0.y;
                acc[2] += exj * f1.x; acc[3] += exj * f1.y;
                acc[4] += exj * f2.x; acc[5] += exj * f2.y;
                acc[6] += exj * f3.x; acc[7] += exj * f3.y;
            }
        }
    }

    #pragma unroll
    for (int c = 0; c < 8; c++) {
        acc[c] += __shfl_xor_sync(0xffffffffu, acc[c], 8);
        acc[c] += __shfl_xor_sync(0xffffffffu, acc[c], 16);
    }
    #pragma unroll
    for (int o = 16; o; o >>= 1) dsum += __shfl_xor_sync(0xffffffffu, dsum, o);

    if (g == 0) {
        float inv = __fdividef(1.f, dsum + 1e-16f);
        // bias is true-column order; h/y are pi-order (position = l8*8 + jj)
        float bb[8];
        #pragma unroll
        for (int jj = 0; jj < 8; jj++)
            bb[jj] = b[PIDX(l8 * 8 + jj)];
        uint4 o;
        ((__half2*)&o)[0] = __floats2half2_rn(fmaxf(acc[0] * inv + bb[0], 0.f),
                                              fmaxf(acc[1] * inv + bb[1], 0.f));
        ((__half2*)&o)[1] = __floats2half2_rn(fmaxf(acc[2] * inv + bb[2], 0.f),
                                              fmaxf(acc[3] * inv + bb[3], 0.f));
        ((__half2*)&o)[2] = __floats2half2_rn(fmaxf(acc[4] * inv + bb[4], 0.f),
                                              fmaxf(acc[5] * inv + bb[5], 0.f));
        ((__half2*)&o)[3] = __floats2half2_rn(fmaxf(acc[6] * inv + bb[6], 0.f),
                                              fmaxf(acc[7] * inv + bb[7], 0.f));
        uint4* y = (uint4*)(dst2 ? g_y2h : g_xh);
        y[(size_t)warp * 8 + l8] = o;
    }
}

// ---------------- output: log_softmax(y2 @ lin_w + lin_b) -----------------------
__global__ void k_out(const float* __restrict__ lw, const float* __restrict__ lb,
                      float* __restrict__ out) {
    __shared__ float sw[HIDC * OUTC];
    __shared__ float sb[OUTC];
    int t = threadIdx.x;
    for (int i = t; i < HIDC * OUTC; i += blockDim.x) {
        int p = i / OUTC, o = i - p * OUTC;
        sw[i] = lw[PIDX(p) * OUTC + o];     // y2 cols are pi-order
    }
    if (t < OUTC) sb[t] = lb[t];
    __syncthreads();

    int warp = t >> 5, lane = t & 31;
    int n = blockIdx.x * (blockDim.x >> 5) + warp;
    if (n >= NN) return;
    const __half2* yr = (const __half2*)(g_y2h + (size_t)n * HIDC);

    int c1 = 32 + (lane & 7);
    float a0 = sb[lane];
    float a1 = sb[c1];
    #pragma unroll
    for (int d2 = 0; d2 < 32; d2++) {
        float2 yv = __half22float2(yr[d2]);
        a0 += yv.x * sw[(2 * d2) * OUTC + lane] + yv.y * sw[(2 * d2 + 1) * OUTC + lane];
        a1 += yv.x * sw[(2 * d2) * OUTC + c1]   + yv.y * sw[(2 * d2 + 1) * OUTC + c1];
    }
    bool v1 = (lane < 8);

    float m = fmaxf(a0, v1 ? a1 : a0);
    #pragma unroll
    for (int o = 16; o; o >>= 1) m = fmaxf(m, __shfl_xor_sync(0xffffffffu, m, o));
    float s = __expf(a0 - m) + (v1 ? __expf(a1 - m) : 0.f);
    #pragma unroll
    for (int o = 16; o; o >>= 1) s += __shfl_xor_sync(0xffffffffu, s, o);
    float ls = logf(s);

    out[(size_t)n * OUTC + lane] = a0 - m - ls;
    if (v1) out[(size_t)n * OUTC + c1] = a1 - m - ls;
}

// ---------------- launch ----------------
extern "C" void kernel_launch(void* const* d_in, const int* in_sizes, int n_in,
                              void* d_out, int out_size) {
    const float* x  = (const float*)d_in[0];
    const int*   ei = (const int*)d_in[1];
    const int*   et = (const int*)d_in[2];
    const float* W1 = (const float*)d_in[4];
    const float* q1 = (const float*)d_in[5];
    const float* k1 = (const float*)d_in[6];
    const float* b1 = (const float*)d_in[7];
    const float* W2 = (const float*)d_in[8];
    const float* q2 = (const float*)d_in[9];
    const float* k2 = (const float*)d_in[10];
    const float* b2 = (const float*)d_in[11];
    const float* lw = (const float*)d_in[12];
    const float* lb = (const float*)d_in[13];
    float* out = (float*)d_out;

    cudaFuncSetAttribute(k_h2, cudaFuncAttributeMaxDynamicSharedMemorySize, KH_SMEM);

    void *degp = nullptr, *flagp = nullptr;
    cudaGetSymbolAddress(&degp, g_deg);
    cudaGetSymbolAddress(&flagp, g_bflag);
    cudaMemsetAsync(degp, 0, NN * sizeof(int));
    cudaMemsetAsync(flagp, 0, 128 * sizeof(int));

    const int nHBlk = (NN + 127) / 128;          // 391

    k_pre<<<EE / 256 + 16, 256>>>(ei, W1, q1, k1, W2, q2, k2);   // 1
    k_scan<<<98, 512>>>();                                       // 2
    k_h2<<<nHBlk, 256, KH_SMEM>>>(x, 0);                         // 3
    k_scatter<<<(EE + 255) / 256, 256>>>(ei, et);                // 4 <- profiled
    k_gat<<<(NN + 7) / 8, 256>>>(b1, 0);                         // 5  -> g_xh (pi)
    k_h2<<<nHBlk, 256, KH_SMEM>>>(nullptr, 1);                   // 6
    k_gat<<<(NN + 7) / 8, 256>>>(b2, 1);                         // 7  -> g_y2h (pi)
    k_out<<<(NN + 7) / 8, 256>>>(lw, lb, out);                   // 8
}

// round 17
// speedup vs baseline: 1.0940x; 1.0940x over previous
#include <cuda_runtime.h>
#include <cuda_fp16.h>
#include <math.h>

#define NN 50000
#define NNP 50176
#define EE 1600000
#define RR 8
#define HIDC 64
#define OUTC 40

// pi layout: stored half position p -> true column
// p = nh*32 + tq*8 + nt*2 + e  ->  col = (nh*4+nt)*8 + tq*2 + e
#define PIDX(p) ((((((p) >> 5) & 1) << 2) + (((p) >> 1) & 3)) * 8 + \
                 ((((p) >> 3) & 3) << 1) + ((p) & 1))
#define SWZ(boff) ((boff) ^ (((boff) >> 3) & 0x70))

// ---------------- scratch (vector-accessed arrays force-aligned) ---------------
__device__ __align__(16) __half g_h[(size_t)RR * NN * HIDC];  // h (fp16, pi-order cols)
__device__ __align__(16) __half g_xh[(size_t)NNP * HIDC];     // layer-2 input (fp16, pi)
__device__ __align__(16) __half g_y2h[(size_t)NN * HIDC];     // layer-2 output (fp16, pi)
__device__ __align__(16) float g_qk[(size_t)NN * 16];         // qn (0..7), kn (8..15)
__device__ __align__(16) __half g_whA[RR * HIDC * HIDC];      // W1 fp16
__device__ __align__(16) __half g_whB[RR * HIDC * HIDC];      // W2 fp16 (rows pi-permuted)
__device__ __align__(16) __half g_wqkhA[64 * 16];             // layer-1 wqk matrix
__device__ __align__(16) __half g_wqkhB[64 * 16];             // layer-2 wqk matrix

// CSR-by-dst (g_csr padded by 32 zero entries for branch-free tails)
__device__ int g_deg[NN];
__device__ int g_incl[NN];
__device__ int g_bsum[128];
__device__ int g_rowptr[NN + 1];
__device__ int g_cursor[NN];
__device__ int g_csr[EE + 32];                   // src | (rel << 16); pad stays 0

// ---------------- k_pre: degree histogram + W1/W2 fp16 conversion + wqk --------
__global__ void k_pre(const int* __restrict__ ei,
                      const float* __restrict__ W1, const float* __restrict__ q1,
                      const float* __restrict__ k1,
                      const float* __restrict__ W2, const float* __restrict__ q2,
                      const float* __restrict__ k2) {
    int b = blockIdx.x, t = threadIdx.x;
    if (b < EE / 256) {                    // 6250 blocks: degree histogram
        int e = b * 256 + t;
        atomicAdd(&g_deg[ei[EE + e]], 1);
        return;
    }
    int rb = b - EE / 256;                 // 0..15
    int r = rb & 7, layer = rb >> 3;
    const float* W = layer ? W2 : W1;
    const float* q = layer ? q2 : q1;
    const float* kk = layer ? k2 : k1;
    __half* wh = layer ? g_whB : g_whA;
    __half* wqk = layer ? g_wqkhB : g_wqkhA;
    int perm = layer;                      // layer-2 input is pi-permuted
    for (int i = t; i < 4096; i += 256) {
        int p = i >> 6, c = i & 63;
        int s = perm ? PIDX(p) : p;
        wh[r * 4096 + p * 64 + c] = __float2half_rn(W[(size_t)r * 4096 + s * 64 + c]);
    }
    if (t < 64) {
        int s = perm ? PIDX(t) : t;
        const float* Wr = W + ((size_t)r * 64 + s) * 64;
        float aq = 0.f, ak = 0.f;
        #pragma unroll
        for (int c = 0; c < 64; c++) {
            float w = Wr[c];
            aq += w * q[r * 64 + c];
            ak += w * kk[r * 64 + c];
        }
        wqk[t * 16 + r]     = __float2half_rn(aq);
        wqk[t * 16 + 8 + r] = __float2half_rn(ak);
    }
}

// ---------------- CSR build ----------------
__global__ void k_scan1() {
    __shared__ int s[512];
    int t = threadIdx.x;
    int idx = blockIdx.x * 512 + t;
    s[t] = (idx < NN) ? g_deg[idx] : 0;
    __syncthreads();
    #pragma unroll
    for (int off = 1; off < 512; off <<= 1) {
        int v = (t >= off) ? s[t - off] : 0;
        __syncthreads();
        s[t] += v;
        __syncthreads();
    }
    if (idx < NN) g_incl[idx] = s[t];
    if (t == 511) g_bsum[blockIdx.x] = s[511];
}

// merged scan2+scan3: every block redundantly scans the 98 block sums in smem
__global__ void k_scan23() {
    __shared__ int sb[128];
    int t = threadIdx.x;
    if (t < 128) sb[t] = (t < 98) ? g_bsum[t] : 0;
    __syncthreads();
    #pragma unroll
    for (int off = 1; off < 128; off <<= 1) {
        int v = (t >= off && t < 128) ? sb[t - off] : 0;
        __syncthreads();
        if (t < 128) sb[t] += v;
        __syncthreads();
    }
    int i = blockIdx.x * 256 + t;
    if (i < NN) {
        int b = i >> 9;
        int off = (b > 0) ? sb[b - 1] : 0;
        int rp = g_incl[i] - g_deg[i] + off;
        g_rowptr[i] = rp;
        g_cursor[i] = rp;
    }
    if (i == 0) g_rowptr[NN] = EE;
}

// vectorized scatter: 4 edges per thread (int4 loads, 4 independent atomic chains)
__global__ void k_scatter(const int* __restrict__ ei, const int* __restrict__ et) {
    int tid = blockIdx.x * blockDim.x + threadIdx.x;    // 0 .. EE/4-1
    if (tid >= EE / 4) return;
    const int4* src4p = (const int4*)ei;
    const int4* dst4p = (const int4*)(ei + EE);
    const int4* et4p  = (const int4*)et;
    int4 s4 = src4p[tid];
    int4 d4 = dst4p[tid];
    int4 r4 = et4p[tid];
    int p0 = atomicAdd(&g_cursor[d4.x], 1);
    int p1 = atomicAdd(&g_cursor[d4.y], 1);
    int p2 = atomicAdd(&g_cursor[d4.z], 1);
    int p3 = atomicAdd(&g_cursor[d4.w], 1);
    g_csr[p0] = s4.x | (r4.x << 16);
    g_csr[p1] = s4.y | (r4.y << 16);
    g_csr[p2] = s4.z | (r4.z << 16);
    g_csr[p3] = s4.w | (r4.w << 16);
}

// ---------------- relation-per-warp HMMA GEMM + MMA-computed qn/kn -------------
__device__ __forceinline__ void ldsm4(unsigned addr, unsigned& r0, unsigned& r1,
                                      unsigned& r2, unsigned& r3) {
    asm volatile("ldmatrix.sync.aligned.m8n8.x4.shared.b16 {%0,%1,%2,%3}, [%4];"
                 : "=r"(r0), "=r"(r1), "=r"(r2), "=r"(r3) : "r"(addr));
}
__device__ __forceinline__ void ldsm4t(unsigned addr, unsigned& r0, unsigned& r1,
                                       unsigned& r2, unsigned& r3) {
    asm volatile("ldmatrix.sync.aligned.m8n8.x4.trans.shared.b16 {%0,%1,%2,%3}, [%4];"
                 : "=r"(r0), "=r"(r1), "=r"(r2), "=r"(r3) : "r"(addr));
}
__device__ __forceinline__ void mma_f16(float* c, unsigned a0, unsigned a1,
                                        unsigned a2, unsigned a3,
                                        unsigned b0, unsigned b1) {
    asm volatile(
        "mma.sync.aligned.m16n8k16.row.col.f32.f16.f16.f32 "
        "{%0,%1,%2,%3}, {%4,%5,%6,%7}, {%8,%9}, {%0,%1,%2,%3};"
        : "+f"(c[0]), "+f"(c[1]), "+f"(c[2]), "+f"(c[3])
        : "r"(a0), "r"(a1), "r"(a2), "r"(a3), "r"(b0), "r"(b1));
}

extern __shared__ char s_dyn[];
#define KH_SMEM (16384 + 65536 + 8192)

// Warp w owns relation w; B-fragments loaded once per n-half, reused over 8 m-tiles.
// layer 0: stage X from fp32 x (convert inline); layer 1: stage from g_xh.
__global__ void __launch_bounds__(256) k_h2(const float* __restrict__ x32, int layer) {
    char* Xs  = s_dyn;                  // 128 x 64 half, swizzled (16 KB)
    char* Ws  = s_dyn + 16384;          // 8 x (64 x 64 half), swizzled (64 KB)
    char* QKs = s_dyn + 16384 + 65536;  // 64 x 16 half, 128B swizzled rows (8 KB)
    const __half* wh = layer ? g_whB : g_whA;
    const __half* wqk = layer ? g_wqkhB : g_wqkhA;
    int n0 = blockIdx.x * 128;
    int tid = threadIdx.x;
    int w = tid >> 5, lane = tid & 31;

    // ---- stage X tile ----
    if (layer) {                        // fp16 padded g_xh: always in-bounds
        const uint4* Xg = (const uint4*)g_xh;
        #pragma unroll
        for (int i = tid; i < 1024; i += 256) {
            int row = i >> 3, c = i & 7;
            *(uint4*)(Xs + SWZ(row * 128 + c * 16)) = Xg[(size_t)(n0 + row) * 8 + c];
        }
    } else {                            // fp32 x -> fp16, bounds-checked
        #pragma unroll
        for (int i = tid; i < 1024; i += 256) {
            int row = i >> 3, c = i & 7;
            int n = n0 + row;
            uint4 u = make_uint4(0, 0, 0, 0);
            if (n < NN) {
                const float4* src = (const float4*)(x32 + (size_t)n * HIDC + c * 8);
                float4 va = src[0], vb = src[1];
                ((__half2*)&u)[0] = __floats2half2_rn(va.x, va.y);
                ((__half2*)&u)[1] = __floats2half2_rn(va.z, va.w);
                ((__half2*)&u)[2] = __floats2half2_rn(vb.x, vb.y);
                ((__half2*)&u)[3] = __floats2half2_rn(vb.z, vb.w);
            }
            *(uint4*)(Xs + SWZ(row * 128 + c * 16)) = u;
        }
    }
    // ---- stage all 8 W (fp16 global, L2 resident) ----
    const uint4* Wg = (const uint4*)wh;
    #pragma unroll
    for (int i = tid; i < 4096; i += 256) {
        int r = i >> 9, row = (i >> 3) & 63, c = i & 7;
        *(uint4*)(Ws + r * 8192 + SWZ(row * 128 + c * 16)) = Wg[i];
    }
    // ---- stage wqk tile ----
    if (tid < 128) {
        int row = tid >> 1, c = tid & 1;
        *(uint4*)(QKs + SWZ(row * 128 + c * 16)) = ((const uint4*)wqk)[tid];
    }
    __syncthreads();

    int j = lane & 7, mat = lane >> 3;
    int mrow = ((mat & 1) << 3) + j;
    int kcol = (mat & 2) << 2;

    unsigned xb  = (unsigned)__cvta_generic_to_shared(Xs);
    unsigned wb  = (unsigned)__cvta_generic_to_shared(Ws);
    unsigned qkb = (unsigned)__cvta_generic_to_shared(QKs);

    int g4 = lane >> 2, tq = lane & 3;
    unsigned wrb = wb + w * 8192;       // this warp's relation
    __half* hb = g_h + (size_t)w * NN * HIDC;

    #pragma unroll
    for (int nh = 0; nh < 2; nh++) {
        // B-fragments for this relation's n-half: kept in registers
        unsigned bf[4][4][2];
        #pragma unroll
        for (int kk = 0; kk < 4; kk++) {
            #pragma unroll
            for (int nbl = 0; nbl < 2; nbl++) {
                int nb = nh * 2 + nbl;
                ldsm4t(wrb + SWZ((kk * 16 + mrow) * 128 + (nb * 16 + kcol) * 2),
                       bf[kk][2 * nbl][0], bf[kk][2 * nbl][1],
                       bf[kk][2 * nbl + 1][0], bf[kk][2 * nbl + 1][1]);
            }
        }

        #pragma unroll
        for (int mt = 0; mt < 8; mt++) {
            unsigned a[4][4];
            #pragma unroll
            for (int kk = 0; kk < 4; kk++)
                ldsm4(xb + SWZ((mt * 16 + mrow) * 128 + (kk * 16 + kcol) * 2),
                      a[kk][0], a[kk][1], a[kk][2], a[kk][3]);

            float cc[4][4];
            #pragma unroll
            for (int nt = 0; nt < 4; nt++)
                #pragma unroll
                for (int z = 0; z < 4; z++) cc[nt][z] = 0.f;
            #pragma unroll
            for (int kk = 0; kk < 4; kk++)
                #pragma unroll
                for (int nt = 0; nt < 4; nt++)
                    mma_f16(cc[nt], a[kk][0], a[kk][1], a[kk][2], a[kk][3],
                            bf[kk][nt][0], bf[kk][nt][1]);

            int nA = n0 + mt * 16 + g4, nB = nA + 8;

            // qn/kn tile: warp w handles m-tile w (first n-half pass only)
            if (nh == 0 && mt == w) {
                float cq[2][4];
                #pragma unroll
                for (int z = 0; z < 4; z++) { cq[0][z] = 0.f; cq[1][z] = 0.f; }
                #pragma unroll
                for (int kk = 0; kk < 4; kk++) {
                    unsigned q0, q1, q2, q3;
                    ldsm4t(qkb + SWZ((kk * 16 + mrow) * 128 + kcol * 2), q0, q1, q2, q3);
                    mma_f16(cq[0], a[kk][0], a[kk][1], a[kk][2], a[kk][3], q0, q1);
                    mma_f16(cq[1], a[kk][0], a[kk][1], a[kk][2], a[kk][3], q2, q3);
                }
                if (nA < NN) {
                    *(float2*)&g_qk[nA * 16 + tq * 2]     = make_float2(cq[0][0], cq[0][1]);
                    *(float2*)&g_qk[nA * 16 + 8 + tq * 2] = make_float2(cq[1][0], cq[1][1]);
                }
                if (nB < NN) {
                    *(float2*)&g_qk[nB * 16 + tq * 2]     = make_float2(cq[0][2], cq[0][3]);
                    *(float2*)&g_qk[nB * 16 + 8 + tq * 2] = make_float2(cq[1][2], cq[1][3]);
                }
            }

            // epilogue: pi-order store, granule = nh*4 + tq (64B-sector aligned)
            uint4 uA, uB;
            ((__half2*)&uA)[0] = __floats2half2_rn(cc[0][0], cc[0][1]);
            ((__half2*)&uA)[1] = __floats2half2_rn(cc[1][0], cc[1][1]);
            ((__half2*)&uA)[2] = __floats2half2_rn(cc[2][0], cc[2][1]);
            ((__half2*)&uA)[3] = __floats2half2_rn(cc[3][0], cc[3][1]);
            ((__half2*)&uB)[0] = __floats2half2_rn(cc[0][2], cc[0][3]);
            ((__half2*)&uB)[1] = __floats2half2_rn(cc[1][2], cc[1][3]);
            ((__half2*)&uB)[2] = __floats2half2_rn(cc[2][2], cc[2][3]);
            ((__half2*)&uB)[3] = __floats2half2_rn(cc[3][2], cc[3][3]);
            if (nA < NN) ((uint4*)(hb + (size_t)nA * HIDC))[nh * 4 + tq] = uA;
            if (nB < NN) ((uint4*)(hb + (size_t)nB * HIDC))[nh * 4 + tq] = uB;
        }
    }
}

// ---------------- fused softmax + aggregation (one warp per dst) ----------------
__global__ void __launch_bounds__(256, 6) k_gat(const float* __restrict__ b, int dst2) {
    int warp = blockIdx.x * 8 + (threadIdx.x >> 5);
    int lane = threadIdx.x & 31;
    if (warp >= NN) return;
    int g = lane >> 3;
    int l8 = lane & 7;

    int beg = g_rowptr[warp];
    int end = g_rowptr[warp + 1];

    float acc[8];
    #pragma unroll
    for (int c = 0; c < 8; c++) acc[c] = 0.f;
    float dsum = 0.f;
    const uint4* h4 = (const uint4*)g_h;

    for (int base = beg; base < end; base += 32) {
        int i = base + lane;
        int pk = g_csr[i];                     // padded: always valid
        int s = pk & 0xFFFF, r = pk >> 16;
        float a = g_qk[warp * 16 + r] + g_qk[s * 16 + 8 + r];
        a = a > 0.f ? a : 0.2f * a;
        float ex = (i < end) ? __expf(a) : 0.f;
        dsum += ex;

        int cnt = end - base;
        if (cnt >= 32) {
            #pragma unroll
            for (int jj = 0; jj < 32; jj += 4) {
                int idx = jj + g;
                float exj = __shfl_sync(0xffffffffu, ex, idx);
                int pkj = __shfl_sync(0xffffffffu, pk, idx);
                int sj = pkj & 0xFFFF, rj = pkj >> 16;
                uint4 v = h4[((size_t)rj * NN + sj) * 8 + l8];
                float2 f0 = __half22float2(*(__half2*)&v.x);
                float2 f1 = __half22float2(*(__half2*)&v.y);
                float2 f2 = __half22float2(*(__half2*)&v.z);
                float2 f3 = __half22float2(*(__half2*)&v.w);
                acc[0] += exj * f0.x; acc[1] += exj * f0.y;
                acc[2] += exj * f1.x; acc[3] += exj * f1.y;
                acc[4] += exj * f2.x; acc[5] += exj * f2.y;
                acc[6] += exj * f3.x; acc[7] += exj * f3.y;
            }
        } else {
            int ng = (cnt + 3) & ~3;
            for (int jj = 0; jj < ng; jj += 4) {
                int idx = jj + g;
                float exj = __shfl_sync(0xffffffffu, ex, idx);   // 0 for idx >= cnt
                int pkj = __shfl_sync(0xffffffffu, pk, idx);
                int sj = pkj & 0xFFFF, rj = pkj >> 16;
                uint4 v = h4[((size_t)rj * NN + sj) * 8 + l8];
                float2 f0 = __half22float2(*(__half2*)&v.x);
                float2 f1 = __half22float2(*(__half2*)&v.y);
                float2 f2 = __half22float2(*(__half2*)&v.z);
                float2 f3 = __half22float2(*(__half2*)&v.w);
                acc[0] += exj * f0.x; acc[1] += exj * f0.y;
                acc[2] += exj * f1.x; acc[3] += exj * f1.y;
                acc[4] += exj * f2.x; acc[5] += exj * f2.y;
                acc[6] += exj * f3.x; acc[7] += exj * f3.y;
            }
        }
    }

    #pragma unroll
    for (int c = 0; c < 8; c++) {
        acc[c] += __shfl_xor_sync(0xffffffffu, acc[c], 8);
        acc[c] += __shfl_xor_sync(0xffffffffu, acc[c], 16);
    }
    #pragma unroll
    for (int o = 16; o; o >>= 1) dsum += __shfl_xor_sync(0xffffffffu, dsum, o);

    if (g == 0) {
        float inv = __fdividef(1.f, dsum + 1e-16f);
        // bias is true-column order; h/y are pi-order (position = l8*8 + jj)
        float bb[8];
        #pragma unroll
        for (int jj = 0; jj < 8; jj++)
            bb[jj] = b[PIDX(l8 * 8 + jj)];
        uint4 o;
        ((__half2*)&o)[0] = __floats2half2_rn(fmaxf(acc[0] * inv + bb[0], 0.f),
                                              fmaxf(acc[1] * inv + bb[1], 0.f));
        ((__half2*)&o)[1] = __floats2half2_rn(fmaxf(acc[2] * inv + bb[2], 0.f),
                                              fmaxf(acc[3] * inv + bb[3], 0.f));
        ((__half2*)&o)[2] = __floats2half2_rn(fmaxf(acc[4] * inv + bb[4], 0.f),
                                              fmaxf(acc[5] * inv + bb[5], 0.f));
        ((__half2*)&o)[3] = __floats2half2_rn(fmaxf(acc[6] * inv + bb[6], 0.f),
                                              fmaxf(acc[7] * inv + bb[7], 0.f));
        uint4* y = (uint4*)(dst2 ? g_y2h : g_xh);
        y[(size_t)warp * 8 + l8] = o;
    }
}

// ---------------- output: log_softmax(y2 @ lin_w + lin_b) -----------------------
__global__ void k_out(const float* __restrict__ lw, const float* __restrict__ lb,
                      float* __restrict__ out) {
    __shared__ float sw[HIDC * OUTC];
    __shared__ float sb[OUTC];
    int t = threadIdx.x;
    for (int i = t; i < HIDC * OUTC; i += blockDim.x) {
        int p = i / OUTC, o = i - p * OUTC;
        sw[i] = lw[PIDX(p) * OUTC + o];     // y2 cols are pi-order
    }
    if (t < OUTC) sb[t] = lb[t];
    __syncthreads();

    int warp = t >> 5, lane = t & 31;
    int n = blockIdx.x * (blockDim.x >> 5) + warp;
    if (n >= NN) return;
    const __half2* yr = (const __half2*)(g_y2h + (size_t)n * HIDC);

    int c1 = 32 + (lane & 7);
    float a0 = sb[lane];
    float a1 = sb[c1];
    #pragma unroll
    for (int d2 = 0; d2 < 32; d2++) {
        float2 yv = __half22float2(yr[d2]);
        a0 += yv.x * sw[(2 * d2) * OUTC + lane] + yv.y * sw[(2 * d2 + 1) * OUTC + lane];
        a1 += yv.x * sw[(2 * d2) * OUTC + c1]   + yv.y * sw[(2 * d2 + 1) * OUTC + c1];
    }
    bool v1 = (lane < 8);

    float m = fmaxf(a0, v1 ? a1 : a0);
    #pragma unroll
    for (int o = 16; o; o >>= 1) m = fmaxf(m, __shfl_xor_sync(0xffffffffu, m, o));
    float s = __expf(a0 - m) + (v1 ? __expf(a1 - m) : 0.f);
    #pragma unroll
    for (int o = 16; o; o >>= 1) s += __shfl_xor_sync(0xffffffffu, s, o);
    float ls = logf(s);

    out[(size_t)n * OUTC + lane] = a0 - m - ls;
    if (v1) out[(size_t)n * OUTC + c1] = a1 - m - ls;
}

// ---------------- launch ----------------
extern "C" void kernel_launch(void* const* d_in, const int* in_sizes, int n_in,
                              void* d_out, int out_size) {
    const float* x  = (const float*)d_in[0];
    const int*   ei = (const int*)d_in[1];
    const int*   et = (const int*)d_in[2];
    const float* W1 = (const float*)d_in[4];
    const float* q1 = (const float*)d_in[5];
    const float* k1 = (const float*)d_in[6];
    const float* b1 = (const float*)d_in[7];
    const float* W2 = (const float*)d_in[8];
    const float* q2 = (const float*)d_in[9];
    const float* k2 = (const float*)d_in[10];
    const float* b2 = (const float*)d_in[11];
    const float* lw = (const float*)d_in[12];
    const float* lb = (const float*)d_in[13];
    float* out = (float*)d_out;

    cudaFuncSetAttribute(k_h2, cudaFuncAttributeMaxDynamicSharedMemorySize, KH_SMEM);

    void* degp = nullptr;
    cudaGetSymbolAddress(&degp, g_deg);
    cudaMemsetAsync(degp, 0, NN * sizeof(int));

    const int nScanBlk = (NN + 511) / 512;       // 98
    const int nHBlk = (NN + 127) / 128;          // 391

    k_pre<<<EE / 256 + 16, 256>>>(ei, W1, q1, k1, W2, q2, k2);   // 1
    k_scan1<<<nScanBlk, 512>>>();                                // 2
    k_scan23<<<(NN + 255) / 256, 256>>>();                       // 3
    k_scatter<<<(EE / 4 + 255) / 256, 256>>>(ei, et);            // 4 <- profiled
    k_h2<<<nHBlk, 256, KH_SMEM>>>(x, 0);                         // 5
    k_gat<<<(NN + 7) / 8, 256>>>(b1, 0);                         // 6  -> g_xh (pi)
    k_h2<<<nHBlk, 256, KH_SMEM>>>(nullptr, 1);                   // 7
    k_gat<<<(NN + 7) / 8, 256>>>(b2, 1);                         // 8  -> g_y2h (pi)
    k_out<<<(NN + 7) / 8, 256>>>(lw, lb, out);                   // 9
}